// round 2
// baseline (speedup 1.0000x reference)
#include <cuda_runtime.h>
#include <cuda_bf16.h>
#include <math.h>

// Problem constants
#define NB   256          // graphs
#define NPG  64           // nodes per graph
#define DEG  8
#define NN   (NB*NPG)     // 16384 nodes
#define NE   (NN*DEG)     // 131072 edges
#define NODE_IN 64
#define EDGE_IN 32
#define HH   256
#define LL   4
#define NHEADS 8
#define DK   32
#define FF   512

// ---------------- scratch (device globals; no allocation allowed) -------------
__device__ float h_buf[(size_t)NN*HH];
__device__ float m_buf[(size_t)NN*HH];
__device__ float q_buf[(size_t)NN*HH];
__device__ float k_buf[(size_t)NN*HH];
__device__ float v_buf[(size_t)NN*HH];
__device__ float ffh_buf[(size_t)NN*FF];
__device__ float ea_buf[(size_t)LL*NE];
__device__ float s1_buf[NN];
__device__ float s2_buf[NN];
__device__ float wa_buf[LL*EDGE_IN];
__device__ float wc_buf[LL];
__device__ float gate_buf[NN];

// ---------------- block reduction (sum, sumsq) over 256 threads ---------------
__device__ __forceinline__ float2 block_reduce_sum2(float a, float b) {
    __shared__ float2 sh[8];
    int lane = threadIdx.x & 31, wid = threadIdx.x >> 5;
    #pragma unroll
    for (int o = 16; o; o >>= 1) {
        a += __shfl_xor_sync(0xffffffffu, a, o);
        b += __shfl_xor_sync(0xffffffffu, b, o);
    }
    if (!lane) sh[wid] = make_float2(a, b);
    __syncthreads();
    if (threadIdx.x == 0) {
        float2 t = make_float2(0.f, 0.f);
        #pragma unroll
        for (int i = 0; i < 8; i++) { t.x += sh[i].x; t.y += sh[i].y; }
        sh[0] = t;
    }
    __syncthreads();
    return sh[0];
}

// ---------------- tiled SGEMM: C = act(A[MxK] @ B[KxN] + bias) ----------------
// BM=BN=64, BK=16, 256 threads, 4x4 per thread. Requires M%64==0, N%64==0, K%16==0.
#define ACT_NONE 0
#define ACT_GELU 1
#define ACT_RELU 2

template<int ACT>
__global__ void sgemm_kernel(const float* __restrict__ A, const float* __restrict__ B,
                             const float* __restrict__ bias, float* __restrict__ C,
                             int M, int Nd, int K) {
    __shared__ float As[16][65];   // [k][m], padded
    __shared__ float Bs[16][64];   // [k][n]
    const int bm = blockIdx.y * 64;
    const int bn = blockIdx.x * 64;
    const int tid = threadIdx.x;
    const int tx = tid & 15, ty = tid >> 4;

    float acc[4][4] = {};

    for (int k0 = 0; k0 < K; k0 += 16) {
        // load A tile 64x16 (float4 per thread)
        {
            int r = tid >> 2;              // 0..63
            int c4 = (tid & 3) * 4;        // 0,4,8,12
            float4 av = *(const float4*)(A + (size_t)(bm + r) * K + k0 + c4);
            As[c4 + 0][r] = av.x; As[c4 + 1][r] = av.y;
            As[c4 + 2][r] = av.z; As[c4 + 3][r] = av.w;
        }
        // load B tile 16x64
        {
            int rb = tid >> 4;             // 0..15
            int cb = (tid & 15) * 4;       // 0..60
            *(float4*)&Bs[rb][cb] = *(const float4*)(B + (size_t)(k0 + rb) * Nd + bn + cb);
        }
        __syncthreads();
        #pragma unroll
        for (int kk = 0; kk < 16; kk++) {
            float4 b4 = *(float4*)&Bs[kk][tx * 4];
            float a0 = As[kk][ty*4+0], a1 = As[kk][ty*4+1];
            float a2 = As[kk][ty*4+2], a3 = As[kk][ty*4+3];
            acc[0][0] += a0*b4.x; acc[0][1] += a0*b4.y; acc[0][2] += a0*b4.z; acc[0][3] += a0*b4.w;
            acc[1][0] += a1*b4.x; acc[1][1] += a1*b4.y; acc[1][2] += a1*b4.z; acc[1][3] += a1*b4.w;
            acc[2][0] += a2*b4.x; acc[2][1] += a2*b4.y; acc[2][2] += a2*b4.z; acc[2][3] += a2*b4.w;
            acc[3][0] += a3*b4.x; acc[3][1] += a3*b4.y; acc[3][2] += a3*b4.z; acc[3][3] += a3*b4.w;
        }
        __syncthreads();
    }

    #pragma unroll
    for (int i = 0; i < 4; i++) {
        int row = bm + ty * 4 + i;
        #pragma unroll
        for (int j = 0; j < 4; j++) {
            int col = bn + tx * 4 + j;
            float v = acc[i][j];
            if (bias) v += bias[col];
            if (ACT == ACT_GELU) v = 0.5f * v * (1.0f + erff(v * 0.70710678118654752f));
            if (ACT == ACT_RELU) v = v > 0.f ? v : 0.f;
            C[(size_t)row * Nd + col] = v;
        }
    }
}

// ---------------- wa[l][j] = sum_k We[j,k]*a3_l[k] ; wc[l] = be . a3_l --------
__global__ void wa_kernel(const float* __restrict__ We, const float* __restrict__ be,
                          const float* __restrict__ gat_a) {
    int t = threadIdx.x;
    if (t < LL * EDGE_IN) {
        int l = t >> 5, j = t & 31;
        const float* a3 = gat_a + l * (3 * HH) + 2 * HH;
        float acc = 0.f;
        for (int k = 0; k < HH; k++) acc += We[(size_t)j * HH + k] * a3[k];
        wa_buf[t] = acc;
    } else if (t < LL * EDGE_IN + LL) {
        int l = t - LL * EDGE_IN;
        const float* a3 = gat_a + l * (3 * HH) + 2 * HH;
        float acc = 0.f;
        for (int k = 0; k < HH; k++) acc += be[k] * a3[k];
        wc_buf[l] = acc;
    }
}

// ---------------- ea[l][e] = edge_feats[e] . wa[l] + wc[l], all 4 layers ------
__global__ void ea_kernel(const float* __restrict__ ef) {
    int e = blockIdx.x * blockDim.x + threadIdx.x;
    if (e >= NE) return;
    float f[EDGE_IN];
    #pragma unroll
    for (int j4 = 0; j4 < 8; j4++) {
        float4 v = *(const float4*)(ef + (size_t)e * EDGE_IN + j4 * 4);
        f[j4*4+0] = v.x; f[j4*4+1] = v.y; f[j4*4+2] = v.z; f[j4*4+3] = v.w;
    }
    #pragma unroll
    for (int l = 0; l < LL; l++) {
        float acc = wc_buf[l];
        #pragma unroll
        for (int j = 0; j < EDGE_IN; j++) acc += f[j] * wa_buf[l * EDGE_IN + j];
        ea_buf[(size_t)l * NE + e] = acc;
    }
}

// ---------------- s1[n] = m[n].a1 ; s2[n] = m[n].a2 (one warp per node) -------
__global__ void s12_kernel(const float* __restrict__ al) {
    int g = blockIdx.x * blockDim.x + threadIdx.x;
    int n = g >> 5, lane = g & 31;
    if (n >= NN) return;
    const float* row = m_buf + (size_t)n * HH;
    float a1 = 0.f, a2 = 0.f;
    #pragma unroll
    for (int c = lane; c < HH; c += 32) {
        float mv = row[c];
        a1 += mv * al[c];
        a2 += mv * al[HH + c];
    }
    #pragma unroll
    for (int o = 16; o; o >>= 1) {
        a1 += __shfl_xor_sync(0xffffffffu, a1, o);
        a2 += __shfl_xor_sync(0xffffffffu, a2, o);
    }
    if (!lane) { s1_buf[n] = a1; s2_buf[n] = a2; }
}

// ------- per-node: 8-edge softmax + gather aggregate + residual + LN ----------
__global__ void gat_edge_kernel(int layer, const int* __restrict__ dst,
                                const float* __restrict__ lng, const float* __restrict__ lnb) {
    int n = blockIdx.x;
    int tid = threadIdx.x;      // 256 = HH
    __shared__ float lg[DEG];
    __shared__ int ds[DEG];
    if (tid < DEG) {
        int d = dst[n * DEG + tid];
        ds[tid] = d;
        float lo = s1_buf[n] + s2_buf[d] + ea_buf[(size_t)layer * NE + n * DEG + tid];
        lg[tid] = lo >= 0.f ? lo : 0.01f * lo;
    }
    __syncthreads();
    float mx = lg[0];
    #pragma unroll
    for (int j = 1; j < DEG; j++) mx = fmaxf(mx, lg[j]);
    float w[DEG], wsum = 0.f;
    #pragma unroll
    for (int j = 0; j < DEG; j++) { w[j] = expf(lg[j] - mx); wsum += w[j]; }
    float inv = 1.f / wsum;
    float agg = 0.f;
    #pragma unroll
    for (int j = 0; j < DEG; j++) agg += w[j] * m_buf[(size_t)ds[j] * HH + tid];
    float v = agg * inv + h_buf[(size_t)n * HH + tid];
    float2 s = block_reduce_sum2(v, v * v);
    float mu = s.x * (1.f / HH);
    float var = s.y * (1.f / HH) - mu * mu;
    h_buf[(size_t)n * HH + tid] = (v - mu) * rsqrtf(var + 1e-5f) * lng[tid] + lnb[tid];
}

// ---------------- global attention: one block per (graph, head) --------------
__global__ void attn_kernel() {
    int blk = blockIdx.x;
    int b = blk >> 3, hd = blk & 7;
    __shared__ float qs[NPG][DK], ks[NPG][DK], vs[NPG][DK];
    __shared__ float sc[NPG][NPG];
    int tid = threadIdx.x;   // 256
    size_t base = (size_t)b * NPG * HH + (size_t)hd * DK;
    for (int e4 = tid; e4 < NPG * (DK / 4); e4 += 256) {
        int i = e4 >> 3, d4 = (e4 & 7) * 4;
        *(float4*)&qs[i][d4] = *(const float4*)(q_buf + base + (size_t)i * HH + d4);
        *(float4*)&ks[i][d4] = *(const float4*)(k_buf + base + (size_t)i * HH + d4);
        *(float4*)&vs[i][d4] = *(const float4*)(v_buf + base + (size_t)i * HH + d4);
    }
    __syncthreads();
    const float scale = 0.17677669529663687f;   // 1/sqrt(32)
    for (int s = tid; s < NPG * NPG; s += 256) {
        int i = s >> 6, k = s & 63;
        float acc = 0.f;
        #pragma unroll
        for (int d = 0; d < DK; d++) acc += qs[i][d] * ks[k][d];
        sc[i][k] = acc * scale;
    }
    __syncthreads();
    if (tid < NPG) {
        float mx = -1e30f;
        #pragma unroll 8
        for (int k = 0; k < NPG; k++) mx = fmaxf(mx, sc[tid][k]);
        float sum = 0.f;
        #pragma unroll 8
        for (int k = 0; k < NPG; k++) { float ev = expf(sc[tid][k] - mx); sc[tid][k] = ev; sum += ev; }
        float inv = 1.f / sum;
        #pragma unroll 8
        for (int k = 0; k < NPG; k++) sc[tid][k] *= inv;
    }
    __syncthreads();
    for (int e = tid; e < NPG * DK; e += 256) {
        int i = e >> 5, d = e & 31;
        float acc = 0.f;
        #pragma unroll
        for (int k = 0; k < NPG; k++) acc += sc[i][k] * vs[k][d];
        m_buf[base + (size_t)i * HH + d] = acc;   // o written to m_buf
    }
}

// ---------------- x = LN(add + x) (in place), per-node block ------------------
__global__ void ln_res_kernel(const float* __restrict__ add, float* __restrict__ x,
                              const float* __restrict__ g, const float* __restrict__ bta,
                              float eps) {
    int n = blockIdx.x, c = threadIdx.x;
    size_t idx = (size_t)n * HH + c;
    float v = add[idx] + x[idx];
    float2 s = block_reduce_sum2(v, v * v);
    float mu = s.x * (1.f / HH);
    float var = s.y * (1.f / HH) - mu * mu;
    x[idx] = (v - mu) * rsqrtf(var + eps) * g[c] + bta[c];
}

// ---------------- gate scalar: gate[n] = relu_t[n] . w + b -------------------
__global__ void gate_kernel(const float* __restrict__ w, const float* __restrict__ b2) {
    int g = blockIdx.x * blockDim.x + threadIdx.x;
    int n = g >> 5, lane = g & 31;
    if (n >= NN) return;
    const float* row = m_buf + (size_t)n * HH;
    float acc = 0.f;
    #pragma unroll
    for (int c = lane; c < HH; c += 32) acc += row[c] * w[c];
    #pragma unroll
    for (int o = 16; o; o >>= 1) acc += __shfl_xor_sync(0xffffffffu, acc, o);
    if (!lane) gate_buf[n] = acc + b2[0];
}

// ---------------- readout: softmax over nodes, weighted sum ------------------
__global__ void readout_kernel(float* __restrict__ out) {
    int b = blockIdx.x, c = threadIdx.x;   // 256 threads
    __shared__ float gsh[NPG];
    __shared__ float es[NPG];
    if (c < NPG) gsh[c] = gate_buf[b * NPG + c];
    __syncthreads();
    float mx = gsh[0];
    #pragma unroll 8
    for (int n = 1; n < NPG; n++) mx = fmaxf(mx, gsh[n]);
    if (c < NPG) es[c] = expf(gsh[c] - mx);
    __syncthreads();
    float sum = 0.f;
    #pragma unroll 8
    for (int n = 0; n < NPG; n++) sum += es[n];
    float inv = 1.f / sum;
    float acc = 0.f;
    for (int n = 0; n < NPG; n++)
        acc += es[n] * h_buf[((size_t)b * NPG + n) * HH + c];
    out[(size_t)b * HH + c] = acc * inv;
}

// =============================================================================
extern "C" void kernel_launch(void* const* d_in, const int* in_sizes, int n_in,
                              void* d_out, int out_size) {
    const float* node_feats = (const float*)d_in[0];
    const float* edge_feats = (const float*)d_in[1];
    // d_in[2] = src (structure is fixed: edges 8n..8n+7 have src n)
    const int*   dst        = (const int*)d_in[3];
    const float* Wn   = (const float*)d_in[4];
    const float* bn   = (const float*)d_in[5];
    const float* We   = (const float*)d_in[6];
    const float* be   = (const float*)d_in[7];
    const float* gatW = (const float*)d_in[8];
    const float* gata = (const float*)d_in[9];
    const float* glng = (const float*)d_in[10];
    const float* glnb = (const float*)d_in[11];
    const float* Wq   = (const float*)d_in[12];
    const float* Wk   = (const float*)d_in[13];
    const float* Wv   = (const float*)d_in[14];
    const float* att_lng = (const float*)d_in[15];
    const float* att_lnb = (const float*)d_in[16];
    const float* ffW1 = (const float*)d_in[17];
    const float* ffb1 = (const float*)d_in[18];
    const float* ffW2 = (const float*)d_in[19];
    const float* ffb2 = (const float*)d_in[20];
    const float* ff_lng = (const float*)d_in[21];
    const float* ff_lnb = (const float*)d_in[22];
    const float* gW1  = (const float*)d_in[23];
    const float* gb1  = (const float*)d_in[24];
    const float* gW2  = (const float*)d_in[25];
    const float* gb2  = (const float*)d_in[26];
    float* out = (float*)d_out;

    float *h = nullptr, *m = nullptr, *q = nullptr, *k = nullptr, *v = nullptr, *ffh = nullptr;
    cudaGetSymbolAddress((void**)&h,   h_buf);
    cudaGetSymbolAddress((void**)&m,   m_buf);
    cudaGetSymbolAddress((void**)&q,   q_buf);
    cudaGetSymbolAddress((void**)&k,   k_buf);
    cudaGetSymbolAddress((void**)&v,   v_buf);
    cudaGetSymbolAddress((void**)&ffh, ffh_buf);

    dim3 gH(HH / 64, NN / 64);    // GEMMs with Nd=256
    dim3 gF(FF / 64, NN / 64);    // GEMM with Nd=512

    // 1) h = node_feats @ Wn + bn
    sgemm_kernel<ACT_NONE><<<gH, 256>>>(node_feats, Wn, bn, h, NN, HH, NODE_IN);
    // 2) edge logits precompute (eliminates e = ef@We+be entirely)
    wa_kernel<<<1, LL * EDGE_IN + LL>>>(We, be, gata);
    ea_kernel<<<NE / 256, 256>>>(edge_feats);

    // 3) GAT layers
    for (int l = 0; l < LL; l++) {
        sgemm_kernel<ACT_NONE><<<gH, 256>>>(h, gatW + (size_t)l * HH * HH, nullptr, m, NN, HH, HH);
        s12_kernel<<<NN * 32 / 256, 256>>>(gata + (size_t)l * 3 * HH);
        gat_edge_kernel<<<NN, 256>>>(l, dst, glng + l * HH, glnb + l * HH);
    }

    // 4) global attention
    sgemm_kernel<ACT_NONE><<<gH, 256>>>(h, Wq, nullptr, q, NN, HH, HH);
    sgemm_kernel<ACT_NONE><<<gH, 256>>>(h, Wk, nullptr, k, NN, HH, HH);
    sgemm_kernel<ACT_NONE><<<gH, 256>>>(h, Wv, nullptr, v, NN, HH, HH);
    attn_kernel<<<NB * NHEADS, 256>>>();                       // o -> m_buf
    ln_res_kernel<<<NN, 256>>>(m, h, att_lng, att_lnb, 1e-6f); // h = LN(o + h)

    // 5) feed-forward
    sgemm_kernel<ACT_GELU><<<gF, 256>>>(h, ffW1, ffb1, ffh, NN, FF, HH);
    sgemm_kernel<ACT_NONE><<<gH, 256>>>(ffh, ffW2, ffb2, q, NN, HH, FF);
    ln_res_kernel<<<NN, 256>>>(q, h, ff_lng, ff_lnb, 1e-6f);   // h = LN(h + y)

    // 6) gating readout
    sgemm_kernel<ACT_RELU><<<gH, 256>>>(h, gW1, gb1, m, NN, HH, HH);
    gate_kernel<<<NN * 32 / 256, 256>>>(gW2, gb2);
    readout_kernel<<<NB, 256>>>(out);
}

// round 3
// speedup vs baseline: 2.1187x; 2.1187x over previous
#include <cuda_runtime.h>
#include <cuda_bf16.h>
#include <math.h>
#include <stdint.h>

// Problem constants
#define NB   256          // graphs
#define NPG  64           // nodes per graph
#define DEG  8
#define NN   (NB*NPG)     // 16384 nodes
#define NE   (NN*DEG)     // 131072 edges
#define NODE_IN 64
#define EDGE_IN 32
#define HH   256
#define LL   4
#define NHEADS 8
#define DK   32
#define FF   512

// ---------------- scratch (device globals; no allocation allowed) -------------
__device__ float h_buf[(size_t)NN*HH];
__device__ float m_buf[(size_t)NN*HH];
__device__ float q_buf[(size_t)NN*HH];
__device__ float k_buf[(size_t)NN*HH];
__device__ float v_buf[(size_t)NN*HH];
__device__ float ea_buf[(size_t)LL*NE];
__device__ float s1_buf[NN];
__device__ float s2_buf[NN];
__device__ float wa_buf[LL*EDGE_IN];
__device__ float wc_buf[LL];
__device__ float gate_buf[NN];

// split-bf16 operand buffers
__device__ __nv_bfloat16 nf_hi[(size_t)NN*NODE_IN], nf_lo[(size_t)NN*NODE_IN];
__device__ __nv_bfloat16 hsp_hi[(size_t)NN*HH],      hsp_lo[(size_t)NN*HH];
__device__ __nv_bfloat16 ffsp_hi[(size_t)NN*FF],     ffsp_lo[(size_t)NN*FF];

// weight split buffer (concatenated)
#define OW_WN   0
#define OW_GAT  (OW_WN + NODE_IN*HH)            // 16384
#define OW_WQ   (OW_GAT + LL*HH*HH)             // +262144
#define OW_WK   (OW_WQ + HH*HH)
#define OW_WV   (OW_WK + HH*HH)
#define OW_FF1  (OW_WV + HH*HH)
#define OW_FF2  (OW_FF1 + HH*FF)
#define OW_G1   (OW_FF2 + FF*HH)
#define OW_TOT  (OW_G1 + HH*HH)
__device__ __nv_bfloat16 w_hi[OW_TOT], w_lo[OW_TOT];

// ---------------- split conversion ----------------
__global__ void conv_split(const float* __restrict__ x, __nv_bfloat16* __restrict__ hi,
                           __nv_bfloat16* __restrict__ lo, int n) {
    int i = blockIdx.x * 256 + threadIdx.x;
    if (i < n) {
        float v = x[i];
        __nv_bfloat16 h = __float2bfloat16(v);
        hi[i] = h;
        lo[i] = __float2bfloat16(v - __bfloat162float(h));
    }
}

__device__ __forceinline__ void split_store(__nv_bfloat16* hi, __nv_bfloat16* lo,
                                            size_t idx, float v) {
    __nv_bfloat16 h = __float2bfloat16(v);
    hi[idx] = h;
    lo[idx] = __float2bfloat16(v - __bfloat162float(h));
}

// ---------------- block reduction (sum, sumsq) over 256 threads ---------------
__device__ __forceinline__ float2 block_reduce_sum2(float a, float b) {
    __shared__ float2 sh[8];
    int lane = threadIdx.x & 31, wid = threadIdx.x >> 5;
    #pragma unroll
    for (int o = 16; o; o >>= 1) {
        a += __shfl_xor_sync(0xffffffffu, a, o);
        b += __shfl_xor_sync(0xffffffffu, b, o);
    }
    if (!lane) sh[wid] = make_float2(a, b);
    __syncthreads();
    if (threadIdx.x == 0) {
        float2 t = make_float2(0.f, 0.f);
        #pragma unroll
        for (int i = 0; i < 8; i++) { t.x += sh[i].x; t.y += sh[i].y; }
        sh[0] = t;
    }
    __syncthreads();
    return sh[0];
}

// ---------------- tensor-core GEMM (bf16 split, 3 MMAs) -----------------------
// C = act(A @ B + bias); A [M,K] fp32-as-(hi+lo bf16), B [K,N] same.
// BM=128, BN=64, BK=32, 256 threads, warp tile 32x32 (m16n8k16).
#define ACT_NONE 0
#define ACT_GELU 1
#define ACT_RELU 2

#define ASTR 136   // uint32 row stride for A smem (==8 mod 32 -> conflict-free frags)
#define BSTR 72    // uint32 row stride for B smem (==8 mod 32)

__device__ __forceinline__ void mma_bf16(float* c, const uint32_t* a, const uint32_t* b) {
    asm volatile(
        "mma.sync.aligned.m16n8k16.row.col.f32.bf16.bf16.f32 "
        "{%0,%1,%2,%3},{%4,%5,%6,%7},{%8,%9},{%0,%1,%2,%3};\n"
        : "+f"(c[0]), "+f"(c[1]), "+f"(c[2]), "+f"(c[3])
        : "r"(a[0]), "r"(a[1]), "r"(a[2]), "r"(a[3]), "r"(b[0]), "r"(b[1]));
}

template<int ACT, bool WC, bool WS>
__global__ void __launch_bounds__(256) mgemm(
    const __nv_bfloat16* __restrict__ Ah, const __nv_bfloat16* __restrict__ Al,
    const __nv_bfloat16* __restrict__ Bh, const __nv_bfloat16* __restrict__ Bl,
    const float* __restrict__ bias, float* __restrict__ C,
    __nv_bfloat16* __restrict__ Ch, __nv_bfloat16* __restrict__ Cl,
    int M, int Nd, int K)
{
    __shared__ uint32_t sAh[16*ASTR], sAl[16*ASTR];
    __shared__ uint32_t sBh[16*BSTR], sBl[16*BSTR];

    const int tid = threadIdx.x;
    const int bm = blockIdx.y * 128, bn = blockIdx.x * 64;
    const int warp = tid >> 5, lane = tid & 31;
    const int g = lane >> 2, tg = lane & 3;
    const int warpM = (warp >> 1) * 32, warpN = (warp & 1) * 32;

    const int arow = tid >> 1, ahalf = tid & 1;     // A loader mapping
    const int bcp = tid >> 4, bcg = tid & 15;       // B loader mapping

    float acc[2][4][4];
    #pragma unroll
    for (int i = 0; i < 2; i++)
        #pragma unroll
        for (int j = 0; j < 4; j++)
            #pragma unroll
            for (int l = 0; l < 4; l++) acc[i][j][l] = 0.f;

    for (int k0 = 0; k0 < K; k0 += 32) {
        // ---- global loads into regs ----
        const uint4* pAh = (const uint4*)(Ah + (size_t)(bm + arow) * K + k0 + ahalf * 16);
        const uint4* pAl = (const uint4*)(Al + (size_t)(bm + arow) * K + k0 + ahalf * 16);
        uint4 aH0 = pAh[0], aH1 = pAh[1];
        uint4 aL0 = pAl[0], aL1 = pAl[1];

        const __nv_bfloat16* pB0h = Bh + (size_t)(k0 + 2 * bcp) * Nd + bn + bcg * 4;
        const __nv_bfloat16* pB0l = Bl + (size_t)(k0 + 2 * bcp) * Nd + bn + bcg * 4;
        uint2 bh0 = *(const uint2*)pB0h, bh1 = *(const uint2*)(pB0h + Nd);
        uint2 bl0 = *(const uint2*)pB0l, bl1 = *(const uint2*)(pB0l + Nd);

        __syncthreads();
        // ---- store A tiles (k-pair packed u32) ----
        {
            uint32_t w0[4] = {aH0.x, aH0.y, aH0.z, aH0.w};
            uint32_t w1[4] = {aH1.x, aH1.y, aH1.z, aH1.w};
            uint32_t v0[4] = {aL0.x, aL0.y, aL0.z, aL0.w};
            uint32_t v1[4] = {aL1.x, aL1.y, aL1.z, aL1.w};
            int cp0 = ahalf * 8;
            #pragma unroll
            for (int i = 0; i < 4; i++) {
                int ii = (i + 2 * ahalf) & 3;   // stagger halves to split banks
                sAh[(cp0 + ii) * ASTR + arow]     = w0[ii];
                sAh[(cp0 + 4 + ii) * ASTR + arow] = w1[ii];
                sAl[(cp0 + ii) * ASTR + arow]     = v0[ii];
                sAl[(cp0 + 4 + ii) * ASTR + arow] = v1[ii];
            }
        }
        // ---- store B tiles: pack (k, k+1) pairs per column ----
        {
            uint32_t pH[4], pL[4];
            pH[0] = __byte_perm(bh0.x, bh1.x, 0x5410);
            pH[1] = __byte_perm(bh0.x, bh1.x, 0x7632);
            pH[2] = __byte_perm(bh0.y, bh1.y, 0x5410);
            pH[3] = __byte_perm(bh0.y, bh1.y, 0x7632);
            pL[0] = __byte_perm(bl0.x, bl1.x, 0x5410);
            pL[1] = __byte_perm(bl0.x, bl1.x, 0x7632);
            pL[2] = __byte_perm(bl0.y, bl1.y, 0x5410);
            pL[3] = __byte_perm(bl0.y, bl1.y, 0x7632);
            #pragma unroll
            for (int j = 0; j < 4; j++) {
                sBh[bcp * BSTR + bcg * 4 + j] = pH[j];
                sBl[bcp * BSTR + bcg * 4 + j] = pL[j];
            }
        }
        __syncthreads();

        // ---- compute: 2 k16 steps ----
        #pragma unroll
        for (int ks = 0; ks < 2; ks++) {
            int cpb = ks * 8 + tg;
            uint32_t afh[2][4], afl[2][4], bfh[4][2], bfl[4][2];
            #pragma unroll
            for (int mt = 0; mt < 2; mt++) {
                int ra = warpM + mt * 16 + g;
                afh[mt][0] = sAh[cpb * ASTR + ra];
                afh[mt][1] = sAh[cpb * ASTR + ra + 8];
                afh[mt][2] = sAh[(cpb + 4) * ASTR + ra];
                afh[mt][3] = sAh[(cpb + 4) * ASTR + ra + 8];
                afl[mt][0] = sAl[cpb * ASTR + ra];
                afl[mt][1] = sAl[cpb * ASTR + ra + 8];
                afl[mt][2] = sAl[(cpb + 4) * ASTR + ra];
                afl[mt][3] = sAl[(cpb + 4) * ASTR + ra + 8];
            }
            #pragma unroll
            for (int nt = 0; nt < 4; nt++) {
                int cb = warpN + nt * 8 + g;
                bfh[nt][0] = sBh[cpb * BSTR + cb];
                bfh[nt][1] = sBh[(cpb + 4) * BSTR + cb];
                bfl[nt][0] = sBl[cpb * BSTR + cb];
                bfl[nt][1] = sBl[(cpb + 4) * BSTR + cb];
            }
            #pragma unroll
            for (int mt = 0; mt < 2; mt++)
                #pragma unroll
                for (int nt = 0; nt < 4; nt++) {
                    mma_bf16(acc[mt][nt], afh[mt], bfh[nt]);
                    mma_bf16(acc[mt][nt], afh[mt], bfl[nt]);
                    mma_bf16(acc[mt][nt], afl[mt], bfh[nt]);
                }
        }
    }

    // ---- epilogue ----
    #pragma unroll
    for (int mt = 0; mt < 2; mt++) {
        int r0 = bm + warpM + mt * 16 + g;
        #pragma unroll
        for (int nt = 0; nt < 4; nt++) {
            int c = bn + warpN + nt * 8 + tg * 2;
            float v00 = acc[mt][nt][0], v01 = acc[mt][nt][1];
            float v10 = acc[mt][nt][2], v11 = acc[mt][nt][3];
            if (bias) { float b0 = bias[c], b1 = bias[c + 1]; v00 += b0; v01 += b1; v10 += b0; v11 += b1; }
            if (ACT == ACT_GELU) {
                v00 = 0.5f * v00 * (1.0f + erff(v00 * 0.70710678118654752f));
                v01 = 0.5f * v01 * (1.0f + erff(v01 * 0.70710678118654752f));
                v10 = 0.5f * v10 * (1.0f + erff(v10 * 0.70710678118654752f));
                v11 = 0.5f * v11 * (1.0f + erff(v11 * 0.70710678118654752f));
            }
            if (ACT == ACT_RELU) {
                v00 = fmaxf(v00, 0.f); v01 = fmaxf(v01, 0.f);
                v10 = fmaxf(v10, 0.f); v11 = fmaxf(v11, 0.f);
            }
            if (WC) {
                *(float2*)(C + (size_t)r0 * Nd + c)       = make_float2(v00, v01);
                *(float2*)(C + (size_t)(r0 + 8) * Nd + c) = make_float2(v10, v11);
            }
            if (WS) {
                split_store(Ch, Cl, (size_t)r0 * Nd + c, v00);
                split_store(Ch, Cl, (size_t)r0 * Nd + c + 1, v01);
                split_store(Ch, Cl, (size_t)(r0 + 8) * Nd + c, v10);
                split_store(Ch, Cl, (size_t)(r0 + 8) * Nd + c + 1, v11);
            }
        }
    }
}

// ---------------- wa[l][j] = sum_k We[j,k]*a3_l[k] ; wc[l] = be . a3_l --------
__global__ void wa_kernel(const float* __restrict__ We, const float* __restrict__ be,
                          const float* __restrict__ gat_a) {
    int t = threadIdx.x;
    if (t < LL * EDGE_IN) {
        int l = t >> 5, j = t & 31;
        const float* a3 = gat_a + l * (3 * HH) + 2 * HH;
        float acc = 0.f;
        for (int k = 0; k < HH; k++) acc += We[(size_t)j * HH + k] * a3[k];
        wa_buf[t] = acc;
    } else if (t < LL * EDGE_IN + LL) {
        int l = t - LL * EDGE_IN;
        const float* a3 = gat_a + l * (3 * HH) + 2 * HH;
        float acc = 0.f;
        for (int k = 0; k < HH; k++) acc += be[k] * a3[k];
        wc_buf[l] = acc;
    }
}

// ---------------- ea[l][e] = edge_feats[e] . wa[l] + wc[l], all 4 layers ------
__global__ void ea_kernel(const float* __restrict__ ef) {
    int e = blockIdx.x * blockDim.x + threadIdx.x;
    if (e >= NE) return;
    float f[EDGE_IN];
    #pragma unroll
    for (int j4 = 0; j4 < 8; j4++) {
        float4 v = *(const float4*)(ef + (size_t)e * EDGE_IN + j4 * 4);
        f[j4*4+0] = v.x; f[j4*4+1] = v.y; f[j4*4+2] = v.z; f[j4*4+3] = v.w;
    }
    #pragma unroll
    for (int l = 0; l < LL; l++) {
        float acc = wc_buf[l];
        #pragma unroll
        for (int j = 0; j < EDGE_IN; j++) acc += f[j] * wa_buf[l * EDGE_IN + j];
        ea_buf[(size_t)l * NE + e] = acc;
    }
}

// ---------------- s1[n] = m[n].a1 ; s2[n] = m[n].a2 (one warp per node) -------
__global__ void s12_kernel(const float* __restrict__ al) {
    int g = blockIdx.x * blockDim.x + threadIdx.x;
    int n = g >> 5, lane = g & 31;
    if (n >= NN) return;
    const float* row = m_buf + (size_t)n * HH;
    float a1 = 0.f, a2 = 0.f;
    #pragma unroll
    for (int c = lane; c < HH; c += 32) {
        float mv = row[c];
        a1 += mv * al[c];
        a2 += mv * al[HH + c];
    }
    #pragma unroll
    for (int o = 16; o; o >>= 1) {
        a1 += __shfl_xor_sync(0xffffffffu, a1, o);
        a2 += __shfl_xor_sync(0xffffffffu, a2, o);
    }
    if (!lane) { s1_buf[n] = a1; s2_buf[n] = a2; }
}

// ------- per-node: 8-edge softmax + gather aggregate + residual + LN ----------
__global__ void gat_edge_kernel(int layer, const int* __restrict__ dst,
                                const float* __restrict__ lng, const float* __restrict__ lnb) {
    int n = blockIdx.x;
    int tid = threadIdx.x;      // 256 = HH
    __shared__ float lg[DEG];
    __shared__ int ds[DEG];
    if (tid < DEG) {
        int d = dst[n * DEG + tid];
        ds[tid] = d;
        float lo = s1_buf[n] + s2_buf[d] + ea_buf[(size_t)layer * NE + n * DEG + tid];
        lg[tid] = lo >= 0.f ? lo : 0.01f * lo;
    }
    __syncthreads();
    float mx = lg[0];
    #pragma unroll
    for (int j = 1; j < DEG; j++) mx = fmaxf(mx, lg[j]);
    float w[DEG], wsum = 0.f;
    #pragma unroll
    for (int j = 0; j < DEG; j++) { w[j] = expf(lg[j] - mx); wsum += w[j]; }
    float inv = 1.f / wsum;
    float agg = 0.f;
    #pragma unroll
    for (int j = 0; j < DEG; j++) agg += w[j] * m_buf[(size_t)ds[j] * HH + tid];
    float v = agg * inv + h_buf[(size_t)n * HH + tid];
    float2 s = block_reduce_sum2(v, v * v);
    float mu = s.x * (1.f / HH);
    float var = s.y * (1.f / HH) - mu * mu;
    float res = (v - mu) * rsqrtf(var + 1e-5f) * lng[tid] + lnb[tid];
    size_t idx = (size_t)n * HH + tid;
    h_buf[idx] = res;
    split_store(hsp_hi, hsp_lo, idx, res);
}

// ---------------- global attention: one block per (graph, head) --------------
__global__ void attn_kernel() {
    int blk = blockIdx.x;
    int b = blk >> 3, hd = blk & 7;
    __shared__ float qs[NPG][DK], ks[NPG][DK], vs[NPG][DK];
    __shared__ float sc[NPG][NPG];
    int tid = threadIdx.x;   // 256
    size_t base = (size_t)b * NPG * HH + (size_t)hd * DK;
    for (int e4 = tid; e4 < NPG * (DK / 4); e4 += 256) {
        int i = e4 >> 3, d4 = (e4 & 7) * 4;
        *(float4*)&qs[i][d4] = *(const float4*)(q_buf + base + (size_t)i * HH + d4);
        *(float4*)&ks[i][d4] = *(const float4*)(k_buf + base + (size_t)i * HH + d4);
        *(float4*)&vs[i][d4] = *(const float4*)(v_buf + base + (size_t)i * HH + d4);
    }
    __syncthreads();
    const float scale = 0.17677669529663687f;   // 1/sqrt(32)
    for (int s = tid; s < NPG * NPG; s += 256) {
        int i = s >> 6, k = s & 63;
        float acc = 0.f;
        #pragma unroll
        for (int d = 0; d < DK; d++) acc += qs[i][d] * ks[k][d];
        sc[i][k] = acc * scale;
    }
    __syncthreads();
    if (tid < NPG) {
        float mx = -1e30f;
        #pragma unroll 8
        for (int k = 0; k < NPG; k++) mx = fmaxf(mx, sc[tid][k]);
        float sum = 0.f;
        #pragma unroll 8
        for (int k = 0; k < NPG; k++) { float ev = expf(sc[tid][k] - mx); sc[tid][k] = ev; sum += ev; }
        float inv = 1.f / sum;
        #pragma unroll 8
        for (int k = 0; k < NPG; k++) sc[tid][k] *= inv;
    }
    __syncthreads();
    for (int e = tid; e < NPG * DK; e += 256) {
        int i = e >> 5, d = e & 31;
        float acc = 0.f;
        #pragma unroll
        for (int k = 0; k < NPG; k++) acc += sc[i][k] * vs[k][d];
        m_buf[base + (size_t)i * HH + d] = acc;   // o written to m_buf
    }
}

// ------ x = LN(add + x) in place; also emits split-bf16 of result ------------
__global__ void ln_res_kernel(const float* __restrict__ add, float* __restrict__ x,
                              const float* __restrict__ g, const float* __restrict__ bta,
                              float eps) {
    int n = blockIdx.x, c = threadIdx.x;
    size_t idx = (size_t)n * HH + c;
    float v = add[idx] + x[idx];
    float2 s = block_reduce_sum2(v, v * v);
    float mu = s.x * (1.f / HH);
    float var = s.y * (1.f / HH) - mu * mu;
    float res = (v - mu) * rsqrtf(var + eps) * g[c] + bta[c];
    x[idx] = res;
    split_store(hsp_hi, hsp_lo, idx, res);
}

// ---------------- gate scalar: gate[n] = relu_t[n] . w + b -------------------
__global__ void gate_kernel(const float* __restrict__ w, const float* __restrict__ b2) {
    int g = blockIdx.x * blockDim.x + threadIdx.x;
    int n = g >> 5, lane = g & 31;
    if (n >= NN) return;
    const float* row = m_buf + (size_t)n * HH;
    float acc = 0.f;
    #pragma unroll
    for (int c = lane; c < HH; c += 32) acc += row[c] * w[c];
    #pragma unroll
    for (int o = 16; o; o >>= 1) acc += __shfl_xor_sync(0xffffffffu, acc, o);
    if (!lane) gate_buf[n] = acc + b2[0];
}

// ---------------- readout: softmax over nodes, weighted sum ------------------
__global__ void readout_kernel(float* __restrict__ out) {
    int b = blockIdx.x, c = threadIdx.x;   // 256 threads
    __shared__ float gsh[NPG];
    __shared__ float es[NPG];
    if (c < NPG) gsh[c] = gate_buf[b * NPG + c];
    __syncthreads();
    float mx = gsh[0];
    #pragma unroll 8
    for (int n = 1; n < NPG; n++) mx = fmaxf(mx, gsh[n]);
    if (c < NPG) es[c] = expf(gsh[c] - mx);
    __syncthreads();
    float sum = 0.f;
    #pragma unroll 8
    for (int n = 0; n < NPG; n++) sum += es[n];
    float inv = 1.f / sum;
    float acc = 0.f;
    for (int n = 0; n < NPG; n++)
        acc += es[n] * h_buf[((size_t)b * NPG + n) * HH + c];
    out[(size_t)b * HH + c] = acc * inv;
}

// =============================================================================
extern "C" void kernel_launch(void* const* d_in, const int* in_sizes, int n_in,
                              void* d_out, int out_size) {
    const float* node_feats = (const float*)d_in[0];
    const float* edge_feats = (const float*)d_in[1];
    const int*   dst        = (const int*)d_in[3];
    const float* Wn   = (const float*)d_in[4];
    const float* bn   = (const float*)d_in[5];
    const float* We   = (const float*)d_in[6];
    const float* be   = (const float*)d_in[7];
    const float* gatW = (const float*)d_in[8];
    const float* gata = (const float*)d_in[9];
    const float* glng = (const float*)d_in[10];
    const float* glnb = (const float*)d_in[11];
    const float* Wq   = (const float*)d_in[12];
    const float* Wk   = (const float*)d_in[13];
    const float* Wv   = (const float*)d_in[14];
    const float* att_lng = (const float*)d_in[15];
    const float* att_lnb = (const float*)d_in[16];
    const float* ffW1 = (const float*)d_in[17];
    const float* ffb1 = (const float*)d_in[18];
    const float* ffW2 = (const float*)d_in[19];
    const float* ffb2 = (const float*)d_in[20];
    const float* ff_lng = (const float*)d_in[21];
    const float* ff_lnb = (const float*)d_in[22];
    const float* gW1  = (const float*)d_in[23];
    const float* gb1  = (const float*)d_in[24];
    const float* gW2  = (const float*)d_in[25];
    const float* gb2  = (const float*)d_in[26];
    float* out = (float*)d_out;

    float *h = nullptr, *m = nullptr, *q = nullptr, *k = nullptr, *v = nullptr;
    __nv_bfloat16 *nfh = nullptr, *nfl = nullptr, *hh = nullptr, *hl = nullptr;
    __nv_bfloat16 *ffh = nullptr, *ffl = nullptr, *wh = nullptr, *wl = nullptr;
    cudaGetSymbolAddress((void**)&h,   h_buf);
    cudaGetSymbolAddress((void**)&m,   m_buf);
    cudaGetSymbolAddress((void**)&q,   q_buf);
    cudaGetSymbolAddress((void**)&k,   k_buf);
    cudaGetSymbolAddress((void**)&v,   v_buf);
    cudaGetSymbolAddress((void**)&nfh, nf_hi);
    cudaGetSymbolAddress((void**)&nfl, nf_lo);
    cudaGetSymbolAddress((void**)&hh,  hsp_hi);
    cudaGetSymbolAddress((void**)&hl,  hsp_lo);
    cudaGetSymbolAddress((void**)&ffh, ffsp_hi);
    cudaGetSymbolAddress((void**)&ffl, ffsp_lo);
    cudaGetSymbolAddress((void**)&wh,  w_hi);
    cudaGetSymbolAddress((void**)&wl,  w_lo);

    // ---- operand conversions ----
    conv_split<<<(NN*NODE_IN + 255)/256, 256>>>(node_feats, nfh, nfl, NN*NODE_IN);
    conv_split<<<(NODE_IN*HH + 255)/256, 256>>>(Wn,   wh + OW_WN,  wl + OW_WN,  NODE_IN*HH);
    conv_split<<<(LL*HH*HH + 255)/256, 256>>>(gatW,   wh + OW_GAT, wl + OW_GAT, LL*HH*HH);
    conv_split<<<(HH*HH + 255)/256, 256>>>(Wq,        wh + OW_WQ,  wl + OW_WQ,  HH*HH);
    conv_split<<<(HH*HH + 255)/256, 256>>>(Wk,        wh + OW_WK,  wl + OW_WK,  HH*HH);
    conv_split<<<(HH*HH + 255)/256, 256>>>(Wv,        wh + OW_WV,  wl + OW_WV,  HH*HH);
    conv_split<<<(HH*FF + 255)/256, 256>>>(ffW1,      wh + OW_FF1, wl + OW_FF1, HH*FF);
    conv_split<<<(FF*HH + 255)/256, 256>>>(ffW2,      wh + OW_FF2, wl + OW_FF2, FF*HH);
    conv_split<<<(HH*HH + 255)/256, 256>>>(gW1,       wh + OW_G1,  wl + OW_G1,  HH*HH);

    dim3 gH(HH/64, NN/128);   // N=256 GEMMs
    dim3 gF(FF/64, NN/128);   // N=512 GEMM

    // 1) h = node_feats @ Wn + bn  (also emit h split)
    mgemm<ACT_NONE, true, true><<<gH, 256>>>(nfh, nfl, wh + OW_WN, wl + OW_WN,
                                             bn, h, hh, hl, NN, HH, NODE_IN);
    // 2) edge logits precompute
    wa_kernel<<<1, LL*EDGE_IN + LL>>>(We, be, gata);
    ea_kernel<<<NE/256, 256>>>(edge_feats);

    // 3) GAT layers
    for (int l = 0; l < LL; l++) {
        mgemm<ACT_NONE, true, false><<<gH, 256>>>(hh, hl, wh + OW_GAT + (size_t)l*HH*HH,
                                                  wl + OW_GAT + (size_t)l*HH*HH,
                                                  nullptr, m, nullptr, nullptr, NN, HH, HH);
        s12_kernel<<<NN*32/256, 256>>>(gata + (size_t)l*3*HH);
        gat_edge_kernel<<<NN, 256>>>(l, dst, glng + l*HH, glnb + l*HH);
    }

    // 4) global attention
    mgemm<ACT_NONE, true, false><<<gH, 256>>>(hh, hl, wh + OW_WQ, wl + OW_WQ, nullptr, q, nullptr, nullptr, NN, HH, HH);
    mgemm<ACT_NONE, true, false><<<gH, 256>>>(hh, hl, wh + OW_WK, wl + OW_WK, nullptr, k, nullptr, nullptr, NN, HH, HH);
    mgemm<ACT_NONE, true, false><<<gH, 256>>>(hh, hl, wh + OW_WV, wl + OW_WV, nullptr, v, nullptr, nullptr, NN, HH, HH);
    attn_kernel<<<NB*NHEADS, 256>>>();                          // o -> m_buf
    ln_res_kernel<<<NN, 256>>>(m, h, att_lng, att_lnb, 1e-6f);  // h = LN(o + h), emits split

    // 5) feed-forward
    mgemm<ACT_GELU, false, true><<<gF, 256>>>(hh, hl, wh + OW_FF1, wl + OW_FF1,
                                              ffb1, nullptr, ffh, ffl, NN, FF, HH);
    mgemm<ACT_NONE, true, false><<<gH, 256>>>(ffh, ffl, wh + OW_FF2, wl + OW_FF2,
                                              ffb2, q, nullptr, nullptr, NN, HH, FF);
    ln_res_kernel<<<NN, 256>>>(q, h, ff_lng, ff_lnb, 1e-6f);    // h = LN(h + y), emits split

    // 6) gating readout
    mgemm<ACT_RELU, true, false><<<gH, 256>>>(hh, hl, wh + OW_G1, wl + OW_G1,
                                              gb1, m, nullptr, nullptr, NN, HH, HH);
    gate_kernel<<<NN*32/256, 256>>>(gW2, gb2);
    readout_kernel<<<NB, 256>>>(out);
}